// round 5
// baseline (speedup 1.0000x reference)
#include <cuda_runtime.h>
#include <cuda_bf16.h>
#include <cstdint>
#include <math.h>

// GELU(x @ W^T + b). Pass 1: split f32 -> bf16 hi/lo device-global scratch.
// Pass 2: 3-term (hh+hl+lh) HMMA GEMM, cp.async 2-stage pipeline, fused GELU.

#define GN   8192
#define GK   512
#define GOUT 512
#define BM   128
#define BN   128
#define KC   32
#define NIT  (GK / KC)          // 16
#define LDT  40                 // smem row stride in bf16 (80B = 5 x 16B)
#define PART_ELE (BM * LDT)     // 5120 bf16 per tile part
#define STAGE_B  (4 * PART_ELE * 2)   // 40960 bytes per stage
#define SMEM_B   (2 * STAGE_B)        // 81920 bytes

#define XN (GN * GK)
#define WN (GOUT * GK)

__device__ __nv_bfloat16 g_Xhi[XN];
__device__ __nv_bfloat16 g_Xlo[XN];
__device__ __nv_bfloat16 g_Whi[WN];
__device__ __nv_bfloat16 g_Wlo[WN];

__device__ __forceinline__ uint32_t smem_u32(const void* p) {
    return (uint32_t)__cvta_generic_to_shared(p);
}
__device__ __forceinline__ void ldmx4(uint32_t* r, uint32_t addr) {
    asm volatile("ldmatrix.sync.aligned.m8n8.x4.shared.b16 {%0,%1,%2,%3}, [%4];"
                 : "=r"(r[0]), "=r"(r[1]), "=r"(r[2]), "=r"(r[3]) : "r"(addr));
}
__device__ __forceinline__ void mma16816(float* c, const uint32_t* a, const uint32_t* b) {
    asm volatile(
        "mma.sync.aligned.m16n8k16.row.col.f32.bf16.bf16.f32 "
        "{%0,%1,%2,%3}, {%4,%5,%6,%7}, {%8,%9}, {%0,%1,%2,%3};"
        : "+f"(c[0]), "+f"(c[1]), "+f"(c[2]), "+f"(c[3])
        : "r"(a[0]), "r"(a[1]), "r"(a[2]), "r"(a[3]), "r"(b[0]), "r"(b[1]));
}
__device__ __forceinline__ void cpasync16(uint32_t dst, const void* src) {
    asm volatile("cp.async.cg.shared.global [%0], [%1], 16;"
                 :: "r"(dst), "l"(src) : "memory");
}
__device__ __forceinline__ void cp_commit() {
    asm volatile("cp.async.commit_group;" ::: "memory");
}
__device__ __forceinline__ void cp_wait1() {
    asm volatile("cp.async.wait_group 1;" ::: "memory");
}
__device__ __forceinline__ void cp_wait0() {
    asm volatile("cp.async.wait_group 0;" ::: "memory");
}
__device__ __forceinline__ void split4(float4 v, uint2& hv, uint2& lv) {
    __nv_bfloat16 h0 = __float2bfloat16(v.x);
    __nv_bfloat16 h1 = __float2bfloat16(v.y);
    __nv_bfloat16 h2 = __float2bfloat16(v.z);
    __nv_bfloat16 h3 = __float2bfloat16(v.w);
    __nv_bfloat16 l0 = __float2bfloat16(v.x - __bfloat162float(h0));
    __nv_bfloat16 l1 = __float2bfloat16(v.y - __bfloat162float(h1));
    __nv_bfloat16 l2 = __float2bfloat16(v.z - __bfloat162float(h2));
    __nv_bfloat16 l3 = __float2bfloat16(v.w - __bfloat162float(h3));
    __nv_bfloat162 hp0(h0, h1), hp1(h2, h3), lp0(l0, l1), lp1(l2, l3);
    hv = make_uint2(*reinterpret_cast<uint32_t*>(&hp0), *reinterpret_cast<uint32_t*>(&hp1));
    lv = make_uint2(*reinterpret_cast<uint32_t*>(&lp0), *reinterpret_cast<uint32_t*>(&lp1));
}

// ---------------- pass 1: f32 -> bf16 hi/lo ----------------
__global__ __launch_bounds__(256)
void convert_kernel(const float* __restrict__ X, const float* __restrict__ W) {
    const int i = blockIdx.x * 256 + threadIdx.x;   // float4 index
    const int nx4 = XN / 4;
    uint2 hv, lv;
    if (i < nx4) {
        float4 v = reinterpret_cast<const float4*>(X)[i];
        split4(v, hv, lv);
        reinterpret_cast<uint2*>(g_Xhi)[i] = hv;
        reinterpret_cast<uint2*>(g_Xlo)[i] = lv;
    } else {
        const int j = i - nx4;
        if (j < WN / 4) {
            float4 v = reinterpret_cast<const float4*>(W)[j];
            split4(v, hv, lv);
            reinterpret_cast<uint2*>(g_Whi)[j] = hv;
            reinterpret_cast<uint2*>(g_Wlo)[j] = lv;
        }
    }
}

// ---------------- pass 2: HMMA GEMM + GELU ----------------
__global__ __launch_bounds__(256, 2)
void gemm_bf16x3_gelu(const float* __restrict__ bias, float* __restrict__ out) {
    extern __shared__ __nv_bfloat16 sm[];   // [2 stages][4 parts][128*LDT]

    const int tid = threadIdx.x;
    const int wid = tid >> 5;
    const int lid = tid & 31;
    const int col0 = blockIdx.x * BN;
    const int row0 = blockIdx.y * BM;

    const int m0 = (wid >> 1) * 32;
    const int n0 = (wid & 1) * 64;
    const int lrow  = lid & 15;
    const int lkoff = (lid >> 4) * 8;

    // cp.async indices: chunk cc in [0,512): row=cc>>2, 16B-col=cc&3
    const int cc0 = tid;           // j even
    const int cc1 = tid + 256;     // j odd
    const int r0_ = cc0 >> 2, c0_ = cc0 & 3;
    const int r1_ = cc1 >> 2, c1_ = cc1 & 3;

    const uint32_t smem_base = smem_u32(sm);

    // ldmatrix base addresses for stage 0 (stage adds STAGE_B bytes)
    uint32_t aHiA[2], aLoA[2], bHiA[4], bLoA[4];
#pragma unroll
    for (int f = 0; f < 2; f++) {
        aHiA[f] = smem_base + (0 * PART_ELE + (m0 + f * 16 + lrow) * LDT) * 2;
        aLoA[f] = smem_base + (1 * PART_ELE + (m0 + f * 16 + lrow) * LDT) * 2;
    }
#pragma unroll
    for (int f = 0; f < 4; f++) {
        bHiA[f] = smem_base + (2 * PART_ELE + (n0 + f * 16 + lrow) * LDT) * 2;
        bLoA[f] = smem_base + (3 * PART_ELE + (n0 + f * 16 + lrow) * LDT) * 2;
    }

    float acc[2][8][4];
#pragma unroll
    for (int mf = 0; mf < 2; mf++)
#pragma unroll
        for (int nf = 0; nf < 8; nf++)
#pragma unroll
            for (int q = 0; q < 4; q++) acc[mf][nf][q] = 0.0f;

    // issue one stage's loads
    auto issue = [&](int stage, int it) {
        const int kt = it * KC;
        const uint32_t so = smem_base + stage * STAGE_B;
        const __nv_bfloat16* srcs[4] = {g_Xhi, g_Xlo, g_Whi, g_Wlo};
#pragma unroll
        for (int p = 0; p < 4; p++) {
            const int grow = (p < 2 ? row0 : col0);
            const __nv_bfloat16* s = srcs[p];
            cpasync16(so + (p * PART_ELE + r0_ * LDT) * 2 + c0_ * 16,
                      s + (size_t)(grow + r0_) * GK + kt + c0_ * 8);
            cpasync16(so + (p * PART_ELE + r1_ * LDT) * 2 + c1_ * 16,
                      s + (size_t)(grow + r1_) * GK + kt + c1_ * 8);
        }
        cp_commit();
    };

    issue(0, 0);
    issue(1, 1);

    for (int it = 0; it < NIT; it++) {
        const int st = it & 1;
        const uint32_t sb = st * STAGE_B;
        if (it == NIT - 1) cp_wait0(); else cp_wait1();
        __syncthreads();

#pragma unroll
        for (int ks = 0; ks < 2; ks++) {
            const uint32_t kb = sb + (uint32_t)(ks * 16 + lkoff) * 2;
            uint32_t ah[2][4], al[2][4];
#pragma unroll
            for (int mf = 0; mf < 2; mf++) {
                ldmx4(ah[mf], aHiA[mf] + kb);
                ldmx4(al[mf], aLoA[mf] + kb);
            }
            uint32_t bh[8][2], bl[8][2];
#pragma unroll
            for (int f = 0; f < 4; f++) {
                uint32_t r4[4];
                ldmx4(r4, bHiA[f] + kb);
                bh[f * 2][0] = r4[0]; bh[f * 2 + 1][0] = r4[1];
                bh[f * 2][1] = r4[2]; bh[f * 2 + 1][1] = r4[3];
                ldmx4(r4, bLoA[f] + kb);
                bl[f * 2][0] = r4[0]; bl[f * 2 + 1][0] = r4[1];
                bl[f * 2][1] = r4[2]; bl[f * 2 + 1][1] = r4[3];
            }
#pragma unroll
            for (int mf = 0; mf < 2; mf++)
#pragma unroll
                for (int nf = 0; nf < 8; nf++) {
                    mma16816(acc[mf][nf], ah[mf], bh[nf]);
                    mma16816(acc[mf][nf], ah[mf], bl[nf]);
                    mma16816(acc[mf][nf], al[mf], bh[nf]);
                }
        }
        __syncthreads();
        if (it + 2 < NIT) issue(st, it + 2);
    }

    // ---- epilogue: +bias, exact GELU, store ----
    const float kInvSqrt2 = 0.70710678118654752440f;
    const int lr = lid >> 2;
    const int lc = (lid & 3) * 2;
#pragma unroll
    for (int mf = 0; mf < 2; mf++) {
#pragma unroll
        for (int nf = 0; nf < 8; nf++) {
            const int col = col0 + n0 + nf * 8 + lc;
            const float2 bv = *reinterpret_cast<const float2*>(bias + col);
            const int ra = row0 + m0 + mf * 16 + lr;
#pragma unroll
            for (int half = 0; half < 2; half++) {
                const int r = ra + half * 8;
                float v0 = acc[mf][nf][half * 2 + 0] + bv.x;
                float v1 = acc[mf][nf][half * 2 + 1] + bv.y;
                float g0 = 0.5f * v0 * (1.0f + erff(v0 * kInvSqrt2));
                float g1 = 0.5f * v1 * (1.0f + erff(v1 * kInvSqrt2));
                *reinterpret_cast<float2*>(out + (size_t)r * GOUT + col) =
                    make_float2(g0, g1);
            }
        }
    }
}

extern "C" void kernel_launch(void* const* d_in, const int* in_sizes, int n_in,
                              void* d_out, int out_size) {
    // metadata order: x, adj (unused), W, b, a (unused)
    const float* X    = (const float*)d_in[0];
    const float* W    = (const float*)d_in[2];
    const float* bias = (const float*)d_in[3];
    float* out        = (float*)d_out;

    const int total4 = XN / 4 + WN / 4;           // 1,114,112
    convert_kernel<<<(total4 + 255) / 256, 256>>>(X, W);

    static bool attr_set = false;
    if (!attr_set) {
        cudaFuncSetAttribute(gemm_bf16x3_gelu,
                             cudaFuncAttributeMaxDynamicSharedMemorySize, SMEM_B);
        attr_set = true;
    }
    dim3 grid(GOUT / BN, GN / BM);   // (4, 64) = 256 CTAs
    gemm_bf16x3_gelu<<<grid, 256, SMEM_B>>>(bias, out);
}